// round 5
// baseline (speedup 1.0000x reference)
#include <cuda_runtime.h>
#include <cuda_bf16.h>
#include <math.h>

#define N_NODES 50000
#define DIM 64
#define E_EDGES 1250000
#define L_LAYERS 3
#define B_BATCH 4096
#define CAT_D 256   // (L+1)*DIM

// ---- scratch (device globals; no allocations allowed) ----
__device__ float g_bufA[N_NODES * DIM];
__device__ float g_bufB[N_NODES * DIM];
__device__ float g_agg [N_NODES * DIM];
__device__ float g_ucat[B_BATCH * CAT_D];
__device__ float g_pcat[B_BATCH * CAT_D];
__device__ float g_ncat[B_BATCH * CAT_D];

// ============================================================
// SpMM scatter: agg[row] += val * x[col], 16 threads per edge,
// float4 loads + red.global.add.v4.f32 (vector L2 reduction).
// ============================================================
__global__ void spmm_kernel(const float* __restrict__ x,
                            const float* __restrict__ vals,
                            const int*   __restrict__ rows,
                            const int*   __restrict__ cols,
                            float*       __restrict__ agg) {
    long long t = (long long)blockIdx.x * blockDim.x + threadIdx.x;
    int e = (int)(t >> 4);
    int c = (int)(t & 15);
    if (e >= E_EDGES) return;
    int   col = __ldg(cols + e);
    int   row = __ldg(rows + e);
    float v   = __ldg(vals + e);
    float4 m = __ldg((const float4*)x + col * 16 + c);
    m.x *= v; m.y *= v; m.z *= v; m.w *= v;
    float4* dst = (float4*)agg + row * 16 + c;
    asm volatile("red.global.add.v4.f32 [%0], {%1,%2,%3,%4};"
                 :: "l"(dst), "f"(m.x), "f"(m.y), "f"(m.z), "f"(m.w)
                 : "memory");
}

// ============================================================
// Dense per-node transform:
//   h = agg + x
//   sx_j = sum_k h_k * W1[j,k] + b1_j
//   t_j  = sum_k x_k * W2[j,k] + b2_j
//   out  = leaky_relu(sx + agg * t, 0.01)
// 256 threads: 4 nodes in flight, thread j%64 = output dim.
// Weights stored transposed in smem -> conflict-free.
// ============================================================
#define NODES_PER_BLOCK 64

__global__ void dense_kernel(const float* __restrict__ x,
                             const float* __restrict__ agg,
                             const float* __restrict__ w1,
                             const float* __restrict__ b1,
                             const float* __restrict__ w2,
                             const float* __restrict__ b2,
                             float*       __restrict__ out) {
    __shared__ float W1t[DIM * DIM];
    __shared__ float W2t[DIM * DIM];
    __shared__ float B1[DIM], B2[DIM];
    __shared__ float hs[4][DIM];
    __shared__ float es[4][DIM];

    int tid = threadIdx.x;
    for (int i = tid; i < DIM * DIM; i += 256) {
        int k = i >> 6, j = i & 63;
        W1t[k * DIM + j] = w1[j * DIM + k];
        W2t[k * DIM + j] = w2[j * DIM + k];
    }
    if (tid < DIM) { B1[tid] = b1[tid]; B2[tid] = b2[tid]; }
    __syncthreads();

    int g = tid >> 6;        // node slot 0..3
    int j = tid & 63;        // output dim
    int base = blockIdx.x * NODES_PER_BLOCK;

    for (int it = 0; it < NODES_PER_BLOCK / 4; it++) {
        int node = base + it * 4 + g;
        float a = 0.f, x0 = 0.f;
        if (node < N_NODES) {
            a  = agg[node * DIM + j];
            x0 = x  [node * DIM + j];
        }
        es[g][j] = x0;
        hs[g][j] = a + x0;
        __syncthreads();

        float s1 = B1[j], s2 = B2[j];
        #pragma unroll
        for (int k = 0; k < DIM; k++) {
            s1 = fmaf(hs[g][k], W1t[k * DIM + j], s1);
            s2 = fmaf(es[g][k], W2t[k * DIM + j], s2);
        }
        float y = s1 + a * s2;
        y = (y > 0.f) ? y : 0.01f * y;
        if (node < N_NODES) out[node * DIM + j] = y;
        __syncthreads();
    }
}

// ============================================================
// Gather user/pos/neg rows of src into the concat buffers
// at column offset stage*DIM.
// ============================================================
__global__ void gather_kernel(const float* __restrict__ src,
                              const int* __restrict__ user,
                              const int* __restrict__ pos,
                              const int* __restrict__ neg,
                              int stage) {
    int t = blockIdx.x * blockDim.x + threadIdx.x;   // 3*B*DIM threads
    if (t >= 3 * B_BATCH * DIM) return;
    int which = t / (B_BATCH * DIM);
    int r = (t / DIM) % B_BATCH;
    int j = t & 63;
    const int* idx = (which == 0) ? user : (which == 1) ? pos : neg;
    float* dst     = (which == 0) ? g_ucat : (which == 1) ? g_pcat : g_ncat;
    dst[r * CAT_D + stage * DIM + j] = src[idx[r] * DIM + j];
}

// ============================================================
// Loss: one warp per sample; 256-dim dots via float4;
// block-level reduction then one atomicAdd per block.
//   loss_b = softplus(-(pl - nl)) = max(-d,0) + log1p(exp(-|d|))
// ============================================================
__global__ void loss_kernel(float* __restrict__ out) {
    __shared__ float partial[8];
    int warp = (blockIdx.x * blockDim.x + threadIdx.x) >> 5;
    int wloc = threadIdx.x >> 5;
    int lane = threadIdx.x & 31;

    float l = 0.f;
    if (warp < B_BATCH) {
        const float4* u = (const float4*)(g_ucat + warp * CAT_D);
        const float4* p = (const float4*)(g_pcat + warp * CAT_D);
        const float4* n = (const float4*)(g_ncat + warp * CAT_D);
        float pd = 0.f, nd = 0.f;
        #pragma unroll
        for (int i = 0; i < 2; i++) {
            float4 uu = u[lane * 2 + i];
            float4 pp = p[lane * 2 + i];
            float4 nn = n[lane * 2 + i];
            pd += uu.x * pp.x + uu.y * pp.y + uu.z * pp.z + uu.w * pp.w;
            nd += uu.x * nn.x + uu.y * nn.y + uu.z * nn.z + uu.w * nn.w;
        }
        #pragma unroll
        for (int o = 16; o; o >>= 1) {
            pd += __shfl_xor_sync(0xFFFFFFFFu, pd, o);
            nd += __shfl_xor_sync(0xFFFFFFFFu, nd, o);
        }
        float d = pd - nd;
        l = fmaxf(-d, 0.f) + log1pf(expf(-fabsf(d)));
    }
    if (lane == 0) partial[wloc] = l;
    __syncthreads();
    if (threadIdx.x == 0) {
        float s = 0.f;
        #pragma unroll
        for (int i = 0; i < 8; i++) s += partial[i];
        atomicAdd(out, s);
    }
}

// ============================================================
extern "C" void kernel_launch(void* const* d_in, const int* in_sizes, int n_in,
                              void* d_out, int out_size) {
    const float* emb  = (const float*)d_in[0];
    const float* w1w  = (const float*)d_in[1];
    const float* w1b  = (const float*)d_in[2];
    const float* w2w  = (const float*)d_in[3];
    const float* w2b  = (const float*)d_in[4];
    const float* vals = (const float*)d_in[5];
    const int*   rows = (const int*)  d_in[6];
    const int*   cols = (const int*)  d_in[7];
    const int*   user = (const int*)  d_in[8];
    const int*   pos  = (const int*)  d_in[9];
    const int*   neg  = (const int*)  d_in[10];
    float* out = (float*)d_out;

    float *bufA, *bufB, *agg;
    cudaGetSymbolAddress((void**)&bufA, g_bufA);
    cudaGetSymbolAddress((void**)&bufB, g_bufB);
    cudaGetSymbolAddress((void**)&agg,  g_agg);

    const int GATHER_GRID = (3 * B_BATCH * DIM + 255) / 256;
    const int SPMM_GRID   = (E_EDGES * 16 + 255) / 256;
    const int DENSE_GRID  = (N_NODES + NODES_PER_BLOCK - 1) / NODES_PER_BLOCK;

    // stage 0 embeddings
    gather_kernel<<<GATHER_GRID, 256>>>(emb, user, pos, neg, 0);

    const float* cur = emb;
    float* nxt = bufA;
    for (int l = 0; l < L_LAYERS; l++) {
        cudaMemsetAsync(agg, 0, sizeof(float) * N_NODES * DIM);
        spmm_kernel<<<SPMM_GRID, 256>>>(cur, vals, rows, cols, agg);
        dense_kernel<<<DENSE_GRID, 256>>>(cur, agg,
                                          w1w + l * DIM * DIM, w1b + l * DIM,
                                          w2w + l * DIM * DIM, w2b + l * DIM,
                                          nxt);
        gather_kernel<<<GATHER_GRID, 256>>>(nxt, user, pos, neg, l + 1);
        cur = nxt;
        nxt = (cur == bufA) ? bufB : bufA;
    }

    cudaMemsetAsync(out, 0, sizeof(float));
    loss_kernel<<<(B_BATCH * 32 + 255) / 256, 256>>>(out);
}

// round 11
// speedup vs baseline: 1.3458x; 1.3458x over previous
#include <cuda_runtime.h>
#include <cuda_bf16.h>
#include <math.h>

#define N_NODES 50000
#define DIM 64
#define E_EDGES 1250000
#define L_LAYERS 3
#define B_BATCH 4096
#define CAT_D 256   // (L+1)*DIM

#define SCAN_BS 512
#define SCAN_NB ((N_NODES + SCAN_BS - 1) / SCAN_BS)   // 98

// ---- scratch (device globals; no allocations allowed) ----
__device__ float g_bufA[N_NODES * DIM];
__device__ float g_bufB[N_NODES * DIM];
__device__ float g_agg [N_NODES * DIM];
__device__ float g_ucat[B_BATCH * CAT_D];
__device__ float g_pcat[B_BATCH * CAT_D];
__device__ float g_ncat[B_BATCH * CAT_D];
// CSR build scratch
__device__ int   g_cnt     [N_NODES];
__device__ int   g_excl    [N_NODES];
__device__ int   g_partial [SCAN_NB];
__device__ int   g_rowstart[N_NODES + 1];
__device__ int   g_cursor  [N_NODES];
__device__ int2  g_epack   [E_EDGES];     // (col, val-bits) sorted by row

// ============================================================
// CSR build: histogram -> exclusive scan (2-level) -> scatter
// ============================================================
__global__ void hist_kernel(const int* __restrict__ rows, int* __restrict__ cnt) {
    int e = blockIdx.x * blockDim.x + threadIdx.x;
    if (e < E_EDGES) atomicAdd(&cnt[rows[e]], 1);
}

__global__ void scan1_kernel(const int* __restrict__ cnt,
                             int* __restrict__ excl, int* __restrict__ partial) {
    __shared__ int s[SCAN_BS];
    int tid = threadIdx.x;
    int i = blockIdx.x * SCAN_BS + tid;
    int v = (i < N_NODES) ? cnt[i] : 0;
    s[tid] = v;
    __syncthreads();
    for (int o = 1; o < SCAN_BS; o <<= 1) {
        int t = (tid >= o) ? s[tid - o] : 0;
        __syncthreads();
        s[tid] += t;
        __syncthreads();
    }
    if (i < N_NODES) excl[i] = s[tid] - v;
    if (tid == SCAN_BS - 1) partial[blockIdx.x] = s[tid];
}

__global__ void scan2_kernel(int* __restrict__ partial) {
    __shared__ int s[128];
    int tid = threadIdx.x;     // 128 threads, SCAN_NB <= 128
    int v = (tid < SCAN_NB) ? partial[tid] : 0;
    s[tid] = v;
    __syncthreads();
    for (int o = 1; o < 128; o <<= 1) {
        int t = (tid >= o) ? s[tid - o] : 0;
        __syncthreads();
        s[tid] += t;
        __syncthreads();
    }
    if (tid < SCAN_NB) partial[tid] = s[tid] - v;   // exclusive
}

__global__ void scan3_kernel(const int* __restrict__ excl,
                             const int* __restrict__ partial,
                             int* __restrict__ rowstart,
                             int* __restrict__ cursor) {
    int i = blockIdx.x * blockDim.x + threadIdx.x;
    if (i < N_NODES) {
        int v = excl[i] + partial[i / SCAN_BS];
        rowstart[i] = v;
        cursor[i]   = v;
    }
    if (i == 0) rowstart[N_NODES] = E_EDGES;
}

__global__ void scatter_kernel(const int* __restrict__ rows,
                               const int* __restrict__ cols,
                               const float* __restrict__ vals,
                               int* __restrict__ cursor,
                               int2* __restrict__ epack) {
    int e = blockIdx.x * blockDim.x + threadIdx.x;
    if (e >= E_EDGES) return;
    int r = rows[e];
    int p = atomicAdd(&cursor[r], 1);
    epack[p] = make_int2(cols[e], __float_as_int(vals[e]));
}

// ============================================================
// Gather-based SpMM: 16 threads per row, register accumulate,
// one float4 store per thread. No atomics, no agg memset.
// ============================================================
__global__ void spmm_csr_kernel(const float* __restrict__ x,
                                const int2* __restrict__ epack,
                                const int* __restrict__ rowstart,
                                float* __restrict__ agg) {
    int t = blockIdx.x * blockDim.x + threadIdx.x;
    int r = t >> 4;
    int c = t & 15;
    if (r >= N_NODES) return;
    int e   = __ldg(rowstart + r);
    int end = __ldg(rowstart + r + 1);
    float4 acc = make_float4(0.f, 0.f, 0.f, 0.f);
    // process 2 edges per iteration for MLP
    for (; e + 1 < end; e += 2) {
        int2 p0 = __ldg(epack + e);
        int2 p1 = __ldg(epack + e + 1);
        float4 x0 = __ldg((const float4*)x + p0.x * 16 + c);
        float4 x1 = __ldg((const float4*)x + p1.x * 16 + c);
        float v0 = __int_as_float(p0.y);
        float v1 = __int_as_float(p1.y);
        acc.x = fmaf(v0, x0.x, acc.x); acc.y = fmaf(v0, x0.y, acc.y);
        acc.z = fmaf(v0, x0.z, acc.z); acc.w = fmaf(v0, x0.w, acc.w);
        acc.x = fmaf(v1, x1.x, acc.x); acc.y = fmaf(v1, x1.y, acc.y);
        acc.z = fmaf(v1, x1.z, acc.z); acc.w = fmaf(v1, x1.w, acc.w);
    }
    if (e < end) {
        int2 p0 = __ldg(epack + e);
        float4 x0 = __ldg((const float4*)x + p0.x * 16 + c);
        float v0 = __int_as_float(p0.y);
        acc.x = fmaf(v0, x0.x, acc.x); acc.y = fmaf(v0, x0.y, acc.y);
        acc.z = fmaf(v0, x0.z, acc.z); acc.w = fmaf(v0, x0.w, acc.w);
    }
    ((float4*)agg)[r * 16 + c] = acc;
}

// ============================================================
// Dense per-node transform (coalesced weight staging, padded
// smem transpose -> conflict-free reads both phases).
// ============================================================
#define NODES_PER_BLOCK 64
#define WPAD 65

__global__ void dense_kernel(const float* __restrict__ x,
                             const float* __restrict__ agg,
                             const float* __restrict__ w1,
                             const float* __restrict__ b1,
                             const float* __restrict__ w2,
                             const float* __restrict__ b2,
                             float*       __restrict__ out) {
    __shared__ float W1t[DIM * WPAD];
    __shared__ float W2t[DIM * WPAD];
    __shared__ float B1[DIM], B2[DIM];
    __shared__ float hs[4][DIM];
    __shared__ float es[4][DIM];

    int tid = threadIdx.x;
    // coalesced gmem read; transposed smem write (padded -> conflict-free)
    for (int i = tid; i < DIM * DIM; i += 256) {
        int j = i >> 6, k = i & 63;          // w[j][k], consecutive k per lane
        W1t[k * WPAD + j] = w1[i];
        W2t[k * WPAD + j] = w2[i];
    }
    if (tid < DIM) { B1[tid] = b1[tid]; B2[tid] = b2[tid]; }
    __syncthreads();

    int g = tid >> 6;        // node slot 0..3
    int j = tid & 63;        // output dim
    int base = blockIdx.x * NODES_PER_BLOCK;

    for (int it = 0; it < NODES_PER_BLOCK / 4; it++) {
        int node = base + it * 4 + g;
        float a = 0.f, x0 = 0.f;
        if (node < N_NODES) {
            a  = agg[node * DIM + j];
            x0 = x  [node * DIM + j];
        }
        es[g][j] = x0;
        hs[g][j] = a + x0;
        __syncthreads();

        float s1 = B1[j], s2 = B2[j];
        #pragma unroll
        for (int k = 0; k < DIM; k++) {
            s1 = fmaf(hs[g][k], W1t[k * WPAD + j], s1);
            s2 = fmaf(es[g][k], W2t[k * WPAD + j], s2);
        }
        float y = s1 + a * s2;
        y = (y > 0.f) ? y : 0.01f * y;
        if (node < N_NODES) out[node * DIM + j] = y;
        __syncthreads();
    }
}

// ============================================================
// Gather user/pos/neg rows of src into the concat buffers.
// ============================================================
__global__ void gather_kernel(const float* __restrict__ src,
                              const int* __restrict__ user,
                              const int* __restrict__ pos,
                              const int* __restrict__ neg,
                              int stage) {
    int t = blockIdx.x * blockDim.x + threadIdx.x;   // 3*B*DIM threads
    if (t >= 3 * B_BATCH * DIM) return;
    int which = t / (B_BATCH * DIM);
    int r = (t / DIM) % B_BATCH;
    int j = t & 63;
    const int* idx = (which == 0) ? user : (which == 1) ? pos : neg;
    float* dst     = (which == 0) ? g_ucat : (which == 1) ? g_pcat : g_ncat;
    dst[r * CAT_D + stage * DIM + j] = src[idx[r] * DIM + j];
}

// ============================================================
// Loss: one warp per sample; stable softplus; one atomic/block.
// ============================================================
__global__ void loss_kernel(float* __restrict__ out) {
    __shared__ float partial[8];
    int warp = (blockIdx.x * blockDim.x + threadIdx.x) >> 5;
    int wloc = threadIdx.x >> 5;
    int lane = threadIdx.x & 31;

    float l = 0.f;
    if (warp < B_BATCH) {
        const float4* u = (const float4*)(g_ucat + warp * CAT_D);
        const float4* p = (const float4*)(g_pcat + warp * CAT_D);
        const float4* n = (const float4*)(g_ncat + warp * CAT_D);
        float pd = 0.f, nd = 0.f;
        #pragma unroll
        for (int i = 0; i < 2; i++) {
            float4 uu = u[lane * 2 + i];
            float4 pp = p[lane * 2 + i];
            float4 nn = n[lane * 2 + i];
            pd += uu.x * pp.x + uu.y * pp.y + uu.z * pp.z + uu.w * pp.w;
            nd += uu.x * nn.x + uu.y * nn.y + uu.z * nn.z + uu.w * nn.w;
        }
        #pragma unroll
        for (int o = 16; o; o >>= 1) {
            pd += __shfl_xor_sync(0xFFFFFFFFu, pd, o);
            nd += __shfl_xor_sync(0xFFFFFFFFu, nd, o);
        }
        float d = pd - nd;
        l = fmaxf(-d, 0.f) + log1pf(expf(-fabsf(d)));
    }
    if (lane == 0) partial[wloc] = l;
    __syncthreads();
    if (threadIdx.x == 0) {
        float s = 0.f;
        #pragma unroll
        for (int i = 0; i < 8; i++) s += partial[i];
        atomicAdd(out, s);
    }
}

// ============================================================
extern "C" void kernel_launch(void* const* d_in, const int* in_sizes, int n_in,
                              void* d_out, int out_size) {
    const float* emb  = (const float*)d_in[0];
    const float* w1w  = (const float*)d_in[1];
    const float* w1b  = (const float*)d_in[2];
    const float* w2w  = (const float*)d_in[3];
    const float* w2b  = (const float*)d_in[4];
    const float* vals = (const float*)d_in[5];
    const int*   rows = (const int*)  d_in[6];
    const int*   cols = (const int*)  d_in[7];
    const int*   user = (const int*)  d_in[8];
    const int*   pos  = (const int*)  d_in[9];
    const int*   neg  = (const int*)  d_in[10];
    float* out = (float*)d_out;

    float *bufA, *bufB, *agg;
    int *cnt, *excl, *part, *rowstart, *cursor;
    int2 *epack;
    cudaGetSymbolAddress((void**)&bufA,     g_bufA);
    cudaGetSymbolAddress((void**)&bufB,     g_bufB);
    cudaGetSymbolAddress((void**)&agg,      g_agg);
    cudaGetSymbolAddress((void**)&cnt,      g_cnt);
    cudaGetSymbolAddress((void**)&excl,     g_excl);
    cudaGetSymbolAddress((void**)&part,     g_partial);
    cudaGetSymbolAddress((void**)&rowstart, g_rowstart);
    cudaGetSymbolAddress((void**)&cursor,   g_cursor);
    cudaGetSymbolAddress((void**)&epack,    g_epack);

    const int GATHER_GRID = (3 * B_BATCH * DIM + 255) / 256;
    const int EDGE_GRID   = (E_EDGES + 255) / 256;
    const int SPMM_GRID   = (N_NODES * 16 + 255) / 256;
    const int DENSE_GRID  = (N_NODES + NODES_PER_BLOCK - 1) / NODES_PER_BLOCK;
    const int NODE_GRID   = (N_NODES + 255) / 256;

    // ---- CSR build (per launch; deterministic work) ----
    cudaMemsetAsync(cnt, 0, sizeof(int) * N_NODES);
    hist_kernel   <<<EDGE_GRID, 256>>>(rows, cnt);
    scan1_kernel  <<<SCAN_NB, SCAN_BS>>>(cnt, excl, part);
    scan2_kernel  <<<1, 128>>>(part);
    scan3_kernel  <<<NODE_GRID, 256>>>(excl, part, rowstart, cursor);
    scatter_kernel<<<EDGE_GRID, 256>>>(rows, cols, vals, cursor, epack);

    // stage 0 embeddings
    gather_kernel<<<GATHER_GRID, 256>>>(emb, user, pos, neg, 0);

    const float* cur = emb;
    float* nxt = bufA;
    for (int l = 0; l < L_LAYERS; l++) {
        spmm_csr_kernel<<<SPMM_GRID, 256>>>(cur, epack, rowstart, agg);
        dense_kernel<<<DENSE_GRID, 256>>>(cur, agg,
                                          w1w + l * DIM * DIM, w1b + l * DIM,
                                          w2w + l * DIM * DIM, w2b + l * DIM,
                                          nxt);
        gather_kernel<<<GATHER_GRID, 256>>>(nxt, user, pos, neg, l + 1);
        cur = nxt;
        nxt = (cur == bufA) ? bufB : bufA;
    }

    cudaMemsetAsync(out, 0, sizeof(float));
    loss_kernel<<<(B_BATCH * 32 + 255) / 256, 256>>>(out);
}

// round 12
// speedup vs baseline: 2.1330x; 1.5849x over previous
#include <cuda_runtime.h>
#include <cuda_bf16.h>
#include <math.h>

#define N_NODES 50000
#define DIM 64
#define E_EDGES 1250000
#define L_LAYERS 3
#define B_BATCH 4096
#define CAT_D 256   // (L+1)*DIM

#define SCAN_BS 512
#define SCAN_NB ((N_NODES + SCAN_BS - 1) / SCAN_BS)   // 98

// ---- scratch (device globals; no allocations allowed) ----
__device__ float g_bufA[N_NODES * DIM];
__device__ float g_bufB[N_NODES * DIM];
__device__ float g_agg [N_NODES * DIM];
__device__ float g_ucat[B_BATCH * CAT_D];
__device__ float g_pcat[B_BATCH * CAT_D];
__device__ float g_ncat[B_BATCH * CAT_D];
// CSR build scratch
__device__ int   g_cnt     [N_NODES];
__device__ int   g_excl    [N_NODES];
__device__ int   g_partial [SCAN_NB];
__device__ int   g_rowstart[N_NODES + 1];
__device__ int   g_cursor  [N_NODES];
__device__ int2  g_epack   [E_EDGES];     // (col, val-bits) sorted by row

// ============================================================
// CSR build: histogram -> exclusive scan (2-level) -> scatter
// ============================================================
__global__ void hist_kernel(const int* __restrict__ rows, int* __restrict__ cnt) {
    int e = blockIdx.x * blockDim.x + threadIdx.x;
    if (e < E_EDGES) atomicAdd(&cnt[rows[e]], 1);
}

__global__ void scan1_kernel(const int* __restrict__ cnt,
                             int* __restrict__ excl, int* __restrict__ partial) {
    __shared__ int s[SCAN_BS];
    int tid = threadIdx.x;
    int i = blockIdx.x * SCAN_BS + tid;
    int v = (i < N_NODES) ? cnt[i] : 0;
    s[tid] = v;
    __syncthreads();
    for (int o = 1; o < SCAN_BS; o <<= 1) {
        int t = (tid >= o) ? s[tid - o] : 0;
        __syncthreads();
        s[tid] += t;
        __syncthreads();
    }
    if (i < N_NODES) excl[i] = s[tid] - v;
    if (tid == SCAN_BS - 1) partial[blockIdx.x] = s[tid];
}

__global__ void scan2_kernel(int* __restrict__ partial) {
    __shared__ int s[128];
    int tid = threadIdx.x;     // 128 threads, SCAN_NB <= 128
    int v = (tid < SCAN_NB) ? partial[tid] : 0;
    s[tid] = v;
    __syncthreads();
    for (int o = 1; o < 128; o <<= 1) {
        int t = (tid >= o) ? s[tid - o] : 0;
        __syncthreads();
        s[tid] += t;
        __syncthreads();
    }
    if (tid < SCAN_NB) partial[tid] = s[tid] - v;   // exclusive
}

__global__ void scan3_kernel(const int* __restrict__ excl,
                             const int* __restrict__ partial,
                             int* __restrict__ rowstart,
                             int* __restrict__ cursor) {
    int i = blockIdx.x * blockDim.x + threadIdx.x;
    if (i < N_NODES) {
        int v = excl[i] + partial[i / SCAN_BS];
        rowstart[i] = v;
        cursor[i]   = v;
    }
    if (i == 0) rowstart[N_NODES] = E_EDGES;
}

__global__ void scatter_kernel(const int* __restrict__ rows,
                               const int* __restrict__ cols,
                               const float* __restrict__ vals,
                               int* __restrict__ cursor,
                               int2* __restrict__ epack) {
    int e = blockIdx.x * blockDim.x + threadIdx.x;
    if (e >= E_EDGES) return;
    int r = rows[e];
    int p = atomicAdd(&cursor[r], 1);
    epack[p] = make_int2(cols[e], __float_as_int(vals[e]));
}

// ============================================================
// Gather-based SpMM: 16 threads per row, register accumulate,
// one float4 store per thread. No atomics, no agg memset.
// ============================================================
__global__ void spmm_csr_kernel(const float* __restrict__ x,
                                const int2* __restrict__ epack,
                                const int* __restrict__ rowstart,
                                float* __restrict__ agg) {
    int t = blockIdx.x * blockDim.x + threadIdx.x;
    int r = t >> 4;
    int c = t & 15;
    if (r >= N_NODES) return;
    int e   = __ldg(rowstart + r);
    int end = __ldg(rowstart + r + 1);
    float4 acc = make_float4(0.f, 0.f, 0.f, 0.f);
    for (; e + 1 < end; e += 2) {
        int2 p0 = __ldg(epack + e);
        int2 p1 = __ldg(epack + e + 1);
        float4 x0 = __ldg((const float4*)x + p0.x * 16 + c);
        float4 x1 = __ldg((const float4*)x + p1.x * 16 + c);
        float v0 = __int_as_float(p0.y);
        float v1 = __int_as_float(p1.y);
        acc.x = fmaf(v0, x0.x, acc.x); acc.y = fmaf(v0, x0.y, acc.y);
        acc.z = fmaf(v0, x0.z, acc.z); acc.w = fmaf(v0, x0.w, acc.w);
        acc.x = fmaf(v1, x1.x, acc.x); acc.y = fmaf(v1, x1.y, acc.y);
        acc.z = fmaf(v1, x1.z, acc.z); acc.w = fmaf(v1, x1.w, acc.w);
    }
    if (e < end) {
        int2 p0 = __ldg(epack + e);
        float4 x0 = __ldg((const float4*)x + p0.x * 16 + c);
        float v0 = __int_as_float(p0.y);
        acc.x = fmaf(v0, x0.x, acc.x); acc.y = fmaf(v0, x0.y, acc.y);
        acc.z = fmaf(v0, x0.z, acc.z); acc.w = fmaf(v0, x0.w, acc.w);
    }
    ((float4*)agg)[r * 16 + c] = acc;
}

// ============================================================
// Dense v2: register-tiled GEMM. Block = 256 thr = 64 nodes x
// 64 dims; each thread computes a 4(dims)x4(nodes) tile.
// Per k: 2x LDS.128 (W cols) + 8 scalar LDS -> 32 FFMA.
//   h = agg + x staged in smem (pitch 65, conflict-free);
//   W transposed Wt[k][j], pitch 68 (16B-aligned float4 rows).
// Epilogue: agg = h - x; y = leaky(s1+b1 + agg*(s2+b2)).
// ============================================================
#define DNPB 64            // nodes per block
#define HP   65            // h/x smem pitch (floats)
#define WP   68            // W smem pitch (floats, 16B-aligned)
#define DENSE_SMEM ((2 * DNPB * HP + 2 * DIM * WP) * 4)   // 68096 B

__global__ void dense_kernel(const float* __restrict__ x,
                             const float* __restrict__ agg,
                             const float* __restrict__ w1,
                             const float* __restrict__ b1,
                             const float* __restrict__ w2,
                             const float* __restrict__ b2,
                             float*       __restrict__ out) {
    extern __shared__ float sm[];
    float* hS  = sm;                          // [DNPB][HP]  h = agg + x
    float* xS  = hS + DNPB * HP;              // [DNPB][HP]  x
    float* w1S = xS + DNPB * HP;              // [DIM][WP]   W1^T
    float* w2S = w1S + DIM * WP;              // [DIM][WP]   W2^T

    int tid = threadIdx.x;
    int nodeBase = blockIdx.x * DNPB;

    // stage W transposed: coalesced gmem read; 4-way-max smem conflicts
    for (int i = tid; i < DIM * DIM; i += 256) {
        int j = i >> 6, k = i & 63;
        w1S[k * WP + j] = w1[i];
        w2S[k * WP + j] = w2[i];
    }
    // stage h = agg + x and x (row-major, padded): float4 gmem reads
    for (int u = tid; u < DNPB * (DIM / 4); u += 256) {
        int n  = u >> 4;          // local node
        int k4 = u & 15;          // float4 unit within row
        int node = nodeBase + n;
        float4 xv = make_float4(0.f, 0.f, 0.f, 0.f);
        float4 av = make_float4(0.f, 0.f, 0.f, 0.f);
        if (node < N_NODES) {
            xv = __ldg((const float4*)x   + node * 16 + k4);
            av = __ldg((const float4*)agg + node * 16 + k4);
        }
        int base = n * HP + k4 * 4;
        xS[base + 0] = xv.x; xS[base + 1] = xv.y;
        xS[base + 2] = xv.z; xS[base + 3] = xv.w;
        hS[base + 0] = xv.x + av.x; hS[base + 1] = xv.y + av.y;
        hS[base + 2] = xv.z + av.z; hS[base + 3] = xv.w + av.w;
    }
    __syncthreads();

    int tn = tid & 15;            // node-tile index
    int tj = tid >> 4;            // dim-tile index
    int n0 = tn * 4;              // local node base
    int j0 = tj * 4;              // output-dim base

    float s1[4][4], s2[4][4];
    #pragma unroll
    for (int a = 0; a < 4; a++)
        #pragma unroll
        for (int b = 0; b < 4; b++) { s1[a][b] = 0.f; s2[a][b] = 0.f; }

    #pragma unroll 16
    for (int k = 0; k < DIM; k++) {
        float4 w1v = *(const float4*)(w1S + k * WP + j0);
        float4 w2v = *(const float4*)(w2S + k * WP + j0);
        const float* w1a = (const float*)&w1v;
        const float* w2a = (const float*)&w2v;
        float hb[4], xb[4];
        #pragma unroll
        for (int b = 0; b < 4; b++) {
            hb[b] = hS[(n0 + b) * HP + k];
            xb[b] = xS[(n0 + b) * HP + k];
        }
        #pragma unroll
        for (int a = 0; a < 4; a++)
            #pragma unroll
            for (int b = 0; b < 4; b++) {
                s1[a][b] = fmaf(w1a[a], hb[b], s1[a][b]);
                s2[a][b] = fmaf(w2a[a], xb[b], s2[a][b]);
            }
    }

    float4 b1v = __ldg((const float4*)(b1 + j0));
    float4 b2v = __ldg((const float4*)(b2 + j0));
    const float* b1a = (const float*)&b1v;
    const float* b2a = (const float*)&b2v;

    #pragma unroll
    for (int b = 0; b < 4; b++) {
        int node = nodeBase + n0 + b;
        if (node >= N_NODES) continue;
        float4 outv;
        float* oa = (float*)&outv;
        #pragma unroll
        for (int a = 0; a < 4; a++) {
            float ag = hS[(n0 + b) * HP + j0 + a] - xS[(n0 + b) * HP + j0 + a];
            float y = (s1[a][b] + b1a[a]) + ag * (s2[a][b] + b2a[a]);
            oa[a] = (y > 0.f) ? y : 0.01f * y;
        }
        *(float4*)(out + node * DIM + j0) = outv;
    }
}

// ============================================================
// Gather user/pos/neg rows of src into the concat buffers.
// ============================================================
__global__ void gather_kernel(const float* __restrict__ src,
                              const int* __restrict__ user,
                              const int* __restrict__ pos,
                              const int* __restrict__ neg,
                              int stage) {
    int t = blockIdx.x * blockDim.x + threadIdx.x;   // 3*B*DIM threads
    if (t >= 3 * B_BATCH * DIM) return;
    int which = t / (B_BATCH * DIM);
    int r = (t / DIM) % B_BATCH;
    int j = t & 63;
    const int* idx = (which == 0) ? user : (which == 1) ? pos : neg;
    float* dst     = (which == 0) ? g_ucat : (which == 1) ? g_pcat : g_ncat;
    dst[r * CAT_D + stage * DIM + j] = src[idx[r] * DIM + j];
}

// ============================================================
// Loss: one warp per sample; stable softplus; one atomic/block.
// ============================================================
__global__ void loss_kernel(float* __restrict__ out) {
    __shared__ float partial[8];
    int warp = (blockIdx.x * blockDim.x + threadIdx.x) >> 5;
    int wloc = threadIdx.x >> 5;
    int lane = threadIdx.x & 31;

    float l = 0.f;
    if (warp < B_BATCH) {
        const float4* u = (const float4*)(g_ucat + warp * CAT_D);
        const float4* p = (const float4*)(g_pcat + warp * CAT_D);
        const float4* n = (const float4*)(g_ncat + warp * CAT_D);
        float pd = 0.f, nd = 0.f;
        #pragma unroll
        for (int i = 0; i < 2; i++) {
            float4 uu = u[lane * 2 + i];
            float4 pp = p[lane * 2 + i];
            float4 nn = n[lane * 2 + i];
            pd += uu.x * pp.x + uu.y * pp.y + uu.z * pp.z + uu.w * pp.w;
            nd += uu.x * nn.x + uu.y * nn.y + uu.z * nn.z + uu.w * nn.w;
        }
        #pragma unroll
        for (int o = 16; o; o >>= 1) {
            pd += __shfl_xor_sync(0xFFFFFFFFu, pd, o);
            nd += __shfl_xor_sync(0xFFFFFFFFu, nd, o);
        }
        float d = pd - nd;
        l = fmaxf(-d, 0.f) + log1pf(expf(-fabsf(d)));
    }
    if (lane == 0) partial[wloc] = l;
    __syncthreads();
    if (threadIdx.x == 0) {
        float s = 0.f;
        #pragma unroll
        for (int i = 0; i < 8; i++) s += partial[i];
        atomicAdd(out, s);
    }
}

// ============================================================
extern "C" void kernel_launch(void* const* d_in, const int* in_sizes, int n_in,
                              void* d_out, int out_size) {
    const float* emb  = (const float*)d_in[0];
    const float* w1w  = (const float*)d_in[1];
    const float* w1b  = (const float*)d_in[2];
    const float* w2w  = (const float*)d_in[3];
    const float* w2b  = (const float*)d_in[4];
    const float* vals = (const float*)d_in[5];
    const int*   rows = (const int*)  d_in[6];
    const int*   cols = (const int*)  d_in[7];
    const int*   user = (const int*)  d_in[8];
    const int*   pos  = (const int*)  d_in[9];
    const int*   neg  = (const int*)  d_in[10];
    float* out = (float*)d_out;

    float *bufA, *bufB, *agg;
    int *cnt, *excl, *part, *rowstart, *cursor;
    int2 *epack;
    cudaGetSymbolAddress((void**)&bufA,     g_bufA);
    cudaGetSymbolAddress((void**)&bufB,     g_bufB);
    cudaGetSymbolAddress((void**)&agg,      g_agg);
    cudaGetSymbolAddress((void**)&cnt,      g_cnt);
    cudaGetSymbolAddress((void**)&excl,     g_excl);
    cudaGetSymbolAddress((void**)&part,     g_partial);
    cudaGetSymbolAddress((void**)&rowstart, g_rowstart);
    cudaGetSymbolAddress((void**)&cursor,   g_cursor);
    cudaGetSymbolAddress((void**)&epack,    g_epack);

    // opt-in smem for dense v2 (idempotent; host-side, capture-safe)
    cudaFuncSetAttribute(dense_kernel,
                         cudaFuncAttributeMaxDynamicSharedMemorySize, DENSE_SMEM);

    const int GATHER_GRID = (3 * B_BATCH * DIM + 255) / 256;
    const int EDGE_GRID   = (E_EDGES + 255) / 256;
    const int SPMM_GRID   = (N_NODES * 16 + 255) / 256;
    const int DENSE_GRID  = (N_NODES + DNPB - 1) / DNPB;
    const int NODE_GRID   = (N_NODES + 255) / 256;

    // ---- CSR build (per launch; deterministic work) ----
    cudaMemsetAsync(cnt, 0, sizeof(int) * N_NODES);
    hist_kernel   <<<EDGE_GRID, 256>>>(rows, cnt);
    scan1_kernel  <<<SCAN_NB, SCAN_BS>>>(cnt, excl, part);
    scan2_kernel  <<<1, 128>>>(part);
    scan3_kernel  <<<NODE_GRID, 256>>>(excl, part, rowstart, cursor);
    scatter_kernel<<<EDGE_GRID, 256>>>(rows, cols, vals, cursor, epack);

    // stage 0 embeddings
    gather_kernel<<<GATHER_GRID, 256>>>(emb, user, pos, neg, 0);

    const float* cur = emb;
    float* nxt = bufA;
    for (int l = 0; l < L_LAYERS; l++) {
        spmm_csr_kernel<<<SPMM_GRID, 256>>>(cur, epack, rowstart, agg);
        dense_kernel<<<DENSE_GRID, 256, DENSE_SMEM>>>(cur, agg,
                                          w1w + l * DIM * DIM, w1b + l * DIM,
                                          w2w + l * DIM * DIM, w2b + l * DIM,
                                          nxt);
        gather_kernel<<<GATHER_GRID, 256>>>(nxt, user, pos, neg, l + 1);
        cur = nxt;
        nxt = (cur == bufA) ? bufB : bufA;
    }

    cudaMemsetAsync(out, 0, sizeof(float));
    loss_kernel<<<(B_BATCH * 32 + 255) / 256, 256>>>(out);
}

// round 14
// speedup vs baseline: 2.2894x; 1.0733x over previous
#include <cuda_runtime.h>
#include <cuda_bf16.h>
#include <math.h>

#define N_NODES 50000
#define DIM 64
#define E_EDGES 1250000
#define L_LAYERS 3
#define B_BATCH 4096

#define SCAN_BS 512
#define SCAN_NB ((N_NODES + SCAN_BS - 1) / SCAN_BS)   // 98

// ---- scratch (device globals; no allocations allowed) ----
__device__ float g_bufA[N_NODES * DIM];
__device__ float g_bufB[N_NODES * DIM];
__device__ float g_bufC[N_NODES * DIM];
__device__ float g_agg [N_NODES * DIM];
// CSR build scratch
__device__ int   g_cnt     [N_NODES];
__device__ int   g_excl    [N_NODES];
__device__ int   g_partial [SCAN_NB];
__device__ int   g_rowstart[N_NODES + 1];
__device__ int   g_cursor  [N_NODES];
__device__ int2  g_epack   [E_EDGES];     // (col, val-bits) sorted by row

// ============================================================
// CSR build: histogram -> exclusive scan (2-level) -> scatter
// ============================================================
__global__ void hist_kernel(const int* __restrict__ rows, int* __restrict__ cnt) {
    int e = blockIdx.x * blockDim.x + threadIdx.x;
    if (e < E_EDGES) atomicAdd(&cnt[rows[e]], 1);
}

__global__ void scan1_kernel(const int* __restrict__ cnt,
                             int* __restrict__ excl, int* __restrict__ partial) {
    __shared__ int s[SCAN_BS];
    int tid = threadIdx.x;
    int i = blockIdx.x * SCAN_BS + tid;
    int v = (i < N_NODES) ? cnt[i] : 0;
    s[tid] = v;
    __syncthreads();
    for (int o = 1; o < SCAN_BS; o <<= 1) {
        int t = (tid >= o) ? s[tid - o] : 0;
        __syncthreads();
        s[tid] += t;
        __syncthreads();
    }
    if (i < N_NODES) excl[i] = s[tid] - v;
    if (tid == SCAN_BS - 1) partial[blockIdx.x] = s[tid];
}

__global__ void scan2_kernel(int* __restrict__ partial) {
    __shared__ int s[128];
    int tid = threadIdx.x;     // 128 threads, SCAN_NB <= 128
    int v = (tid < SCAN_NB) ? partial[tid] : 0;
    s[tid] = v;
    __syncthreads();
    for (int o = 1; o < 128; o <<= 1) {
        int t = (tid >= o) ? s[tid - o] : 0;
        __syncthreads();
        s[tid] += t;
        __syncthreads();
    }
    if (tid < SCAN_NB) partial[tid] = s[tid] - v;   // exclusive
}

__global__ void scan3_kernel(const int* __restrict__ excl,
                             const int* __restrict__ partial,
                             int* __restrict__ rowstart,
                             int* __restrict__ cursor) {
    int i = blockIdx.x * blockDim.x + threadIdx.x;
    if (i < N_NODES) {
        int v = excl[i] + partial[i / SCAN_BS];
        rowstart[i] = v;
        cursor[i]   = v;
    }
    if (i == 0) rowstart[N_NODES] = E_EDGES;
}

__global__ void scatter_kernel(const int* __restrict__ rows,
                               const int* __restrict__ cols,
                               const float* __restrict__ vals,
                               int* __restrict__ cursor,
                               int2* __restrict__ epack) {
    int e = blockIdx.x * blockDim.x + threadIdx.x;
    if (e >= E_EDGES) return;
    int r = rows[e];
    int p = atomicAdd(&cursor[r], 1);
    epack[p] = make_int2(cols[e], __float_as_int(vals[e]));
}

// ============================================================
// Gather-based SpMM: 16 threads per row, register accumulate,
// one float4 store per thread. No atomics, no agg memset.
// ============================================================
__global__ void spmm_csr_kernel(const float* __restrict__ x,
                                const int2* __restrict__ epack,
                                const int* __restrict__ rowstart,
                                float* __restrict__ agg) {
    int t = blockIdx.x * blockDim.x + threadIdx.x;
    int r = t >> 4;
    int c = t & 15;
    if (r >= N_NODES) return;
    int e   = __ldg(rowstart + r);
    int end = __ldg(rowstart + r + 1);
    float4 acc = make_float4(0.f, 0.f, 0.f, 0.f);
    for (; e + 1 < end; e += 2) {
        int2 p0 = __ldg(epack + e);
        int2 p1 = __ldg(epack + e + 1);
        float4 x0 = __ldg((const float4*)x + p0.x * 16 + c);
        float4 x1 = __ldg((const float4*)x + p1.x * 16 + c);
        float v0 = __int_as_float(p0.y);
        float v1 = __int_as_float(p1.y);
        acc.x = fmaf(v0, x0.x, acc.x); acc.y = fmaf(v0, x0.y, acc.y);
        acc.z = fmaf(v0, x0.z, acc.z); acc.w = fmaf(v0, x0.w, acc.w);
        acc.x = fmaf(v1, x1.x, acc.x); acc.y = fmaf(v1, x1.y, acc.y);
        acc.z = fmaf(v1, x1.z, acc.z); acc.w = fmaf(v1, x1.w, acc.w);
    }
    if (e < end) {
        int2 p0 = __ldg(epack + e);
        float4 x0 = __ldg((const float4*)x + p0.x * 16 + c);
        float v0 = __int_as_float(p0.y);
        acc.x = fmaf(v0, x0.x, acc.x); acc.y = fmaf(v0, x0.y, acc.y);
        acc.z = fmaf(v0, x0.z, acc.z); acc.w = fmaf(v0, x0.w, acc.w);
    }
    ((float4*)agg)[r * 16 + c] = acc;
}

// ============================================================
// Dense v2: register-tiled GEMM. Block = 256 thr = 64 nodes x
// 64 dims; each thread computes a 4(dims)x4(nodes) tile.
// ============================================================
#define DNPB 64            // nodes per block
#define HP   65            // h/x smem pitch (floats)
#define WP   68            // W smem pitch (floats, 16B-aligned)
#define DENSE_SMEM ((2 * DNPB * HP + 2 * DIM * WP) * 4)   // 68096 B

__global__ void dense_kernel(const float* __restrict__ x,
                             const float* __restrict__ agg,
                             const float* __restrict__ w1,
                             const float* __restrict__ b1,
                             const float* __restrict__ w2,
                             const float* __restrict__ b2,
                             float*       __restrict__ out) {
    extern __shared__ float sm[];
    float* hS  = sm;                          // [DNPB][HP]  h = agg + x
    float* xS  = hS + DNPB * HP;              // [DNPB][HP]  x
    float* w1S = xS + DNPB * HP;              // [DIM][WP]   W1^T
    float* w2S = w1S + DIM * WP;              // [DIM][WP]   W2^T

    int tid = threadIdx.x;
    int nodeBase = blockIdx.x * DNPB;

    for (int i = tid; i < DIM * DIM; i += 256) {
        int j = i >> 6, k = i & 63;
        w1S[k * WP + j] = w1[i];
        w2S[k * WP + j] = w2[i];
    }
    for (int u = tid; u < DNPB * (DIM / 4); u += 256) {
        int n  = u >> 4;
        int k4 = u & 15;
        int node = nodeBase + n;
        float4 xv = make_float4(0.f, 0.f, 0.f, 0.f);
        float4 av = make_float4(0.f, 0.f, 0.f, 0.f);
        if (node < N_NODES) {
            xv = __ldg((const float4*)x   + node * 16 + k4);
            av = __ldg((const float4*)agg + node * 16 + k4);
        }
        int base = n * HP + k4 * 4;
        xS[base + 0] = xv.x; xS[base + 1] = xv.y;
        xS[base + 2] = xv.z; xS[base + 3] = xv.w;
        hS[base + 0] = xv.x + av.x; hS[base + 1] = xv.y + av.y;
        hS[base + 2] = xv.z + av.z; hS[base + 3] = xv.w + av.w;
    }
    __syncthreads();

    int tn = tid & 15;
    int tj = tid >> 4;
    int n0 = tn * 4;
    int j0 = tj * 4;

    float s1[4][4], s2[4][4];
    #pragma unroll
    for (int a = 0; a < 4; a++)
        #pragma unroll
        for (int b = 0; b < 4; b++) { s1[a][b] = 0.f; s2[a][b] = 0.f; }

    #pragma unroll 16
    for (int k = 0; k < DIM; k++) {
        float4 w1v = *(const float4*)(w1S + k * WP + j0);
        float4 w2v = *(const float4*)(w2S + k * WP + j0);
        const float* w1a = (const float*)&w1v;
        const float* w2a = (const float*)&w2v;
        float hb[4], xb[4];
        #pragma unroll
        for (int b = 0; b < 4; b++) {
            hb[b] = hS[(n0 + b) * HP + k];
            xb[b] = xS[(n0 + b) * HP + k];
        }
        #pragma unroll
        for (int a = 0; a < 4; a++)
            #pragma unroll
            for (int b = 0; b < 4; b++) {
                s1[a][b] = fmaf(w1a[a], hb[b], s1[a][b]);
                s2[a][b] = fmaf(w2a[a], xb[b], s2[a][b]);
            }
    }

    float4 b1v = __ldg((const float4*)(b1 + j0));
    float4 b2v = __ldg((const float4*)(b2 + j0));
    const float* b1a = (const float*)&b1v;
    const float* b2a = (const float*)&b2v;

    #pragma unroll
    for (int b = 0; b < 4; b++) {
        int node = nodeBase + n0 + b;
        if (node >= N_NODES) continue;
        float4 outv;
        float* oa = (float*)&outv;
        #pragma unroll
        for (int a = 0; a < 4; a++) {
            float ag = hS[(n0 + b) * HP + j0 + a] - xS[(n0 + b) * HP + j0 + a];
            float y = (s1[a][b] + b1a[a]) + ag * (s2[a][b] + b2a[a]);
            oa[a] = (y > 0.f) ? y : 0.01f * y;
        }
        *(float4*)(out + node * DIM + j0) = outv;
    }
}

// ============================================================
// Loss v2: reads u/p/n rows DIRECTLY from the 4 stage buffers
// (no gather kernels, no concat buffers). One warp per sample;
// each lane covers one float2 of each 64-dim vector per stage.
// ============================================================
__global__ void loss_kernel(const float* __restrict__ s0,
                            const float* __restrict__ s1v,
                            const float* __restrict__ s2v,
                            const float* __restrict__ s3v,
                            const int* __restrict__ user,
                            const int* __restrict__ pos,
                            const int* __restrict__ neg,
                            float* __restrict__ out) {
    __shared__ float partial[8];
    int warp = (blockIdx.x * blockDim.x + threadIdx.x) >> 5;
    int wloc = threadIdx.x >> 5;
    int lane = threadIdx.x & 31;

    float l = 0.f;
    if (warp < B_BATCH) {
        const float* bufs[4] = {s0, s1v, s2v, s3v};
        int ui = __ldg(user + warp) * DIM;
        int pi = __ldg(pos  + warp) * DIM;
        int ni = __ldg(neg  + warp) * DIM;
        float pd = 0.f, nd = 0.f;
        #pragma unroll
        for (int s = 0; s < 4; s++) {
            float2 uu = *(const float2*)(bufs[s] + ui + lane * 2);
            float2 pp = *(const float2*)(bufs[s] + pi + lane * 2);
            float2 nn = *(const float2*)(bufs[s] + ni + lane * 2);
            pd += uu.x * pp.x + uu.y * pp.y;
            nd += uu.x * nn.x + uu.y * nn.y;
        }
        #pragma unroll
        for (int o = 16; o; o >>= 1) {
            pd += __shfl_xor_sync(0xFFFFFFFFu, pd, o);
            nd += __shfl_xor_sync(0xFFFFFFFFu, nd, o);
        }
        float d = pd - nd;
        l = fmaxf(-d, 0.f) + log1pf(expf(-fabsf(d)));
    }
    if (lane == 0) partial[wloc] = l;
    __syncthreads();
    if (threadIdx.x == 0) {
        float s = 0.f;
        #pragma unroll
        for (int i = 0; i < 8; i++) s += partial[i];
        atomicAdd(out, s);
    }
}

// ============================================================
extern "C" void kernel_launch(void* const* d_in, const int* in_sizes, int n_in,
                              void* d_out, int out_size) {
    const float* emb  = (const float*)d_in[0];
    const float* w1w  = (const float*)d_in[1];
    const float* w1b  = (const float*)d_in[2];
    const float* w2w  = (const float*)d_in[3];
    const float* w2b  = (const float*)d_in[4];
    const float* vals = (const float*)d_in[5];
    const int*   rows = (const int*)  d_in[6];
    const int*   cols = (const int*)  d_in[7];
    const int*   user = (const int*)  d_in[8];
    const int*   pos  = (const int*)  d_in[9];
    const int*   neg  = (const int*)  d_in[10];
    float* out = (float*)d_out;

    float *bufA, *bufB, *bufC, *agg;
    int *cnt, *excl, *part, *rowstart, *cursor;
    int2 *epack;
    cudaGetSymbolAddress((void**)&bufA,     g_bufA);
    cudaGetSymbolAddress((void**)&bufB,     g_bufB);
    cudaGetSymbolAddress((void**)&bufC,     g_bufC);
    cudaGetSymbolAddress((void**)&agg,      g_agg);
    cudaGetSymbolAddress((void**)&cnt,      g_cnt);
    cudaGetSymbolAddress((void**)&excl,     g_excl);
    cudaGetSymbolAddress((void**)&part,     g_partial);
    cudaGetSymbolAddress((void**)&rowstart, g_rowstart);
    cudaGetSymbolAddress((void**)&cursor,   g_cursor);
    cudaGetSymbolAddress((void**)&epack,    g_epack);

    cudaFuncSetAttribute(dense_kernel,
                         cudaFuncAttributeMaxDynamicSharedMemorySize, DENSE_SMEM);

    const int EDGE_GRID   = (E_EDGES + 255) / 256;
    const int SPMM_GRID   = (N_NODES * 16 + 255) / 256;
    const int DENSE_GRID  = (N_NODES + DNPB - 1) / DNPB;
    const int NODE_GRID   = (N_NODES + 255) / 256;

    // ---- CSR build (per launch; deterministic work) ----
    cudaMemsetAsync(cnt, 0, sizeof(int) * N_NODES);
    hist_kernel   <<<EDGE_GRID, 256>>>(rows, cnt);
    scan1_kernel  <<<SCAN_NB, SCAN_BS>>>(cnt, excl, part);
    scan2_kernel  <<<1, 128>>>(part);
    scan3_kernel  <<<NODE_GRID, 256>>>(excl, part, rowstart, cursor);
    scatter_kernel<<<EDGE_GRID, 256>>>(rows, cols, vals, cursor, epack);

    // ---- layers: emb -> bufA -> bufB -> bufC (all kept live) ----
    float* outs[L_LAYERS] = {bufA, bufB, bufC};
    const float* cur = emb;
    for (int l = 0; l < L_LAYERS; l++) {
        spmm_csr_kernel<<<SPMM_GRID, 256>>>(cur, epack, rowstart, agg);
        dense_kernel<<<DENSE_GRID, 256, DENSE_SMEM>>>(cur, agg,
                                          w1w + l * DIM * DIM, w1b + l * DIM,
                                          w2w + l * DIM * DIM, w2b + l * DIM,
                                          outs[l]);
        cur = outs[l];
    }

    cudaMemsetAsync(out, 0, sizeof(float));
    loss_kernel<<<(B_BATCH * 32 + 255) / 256, 256>>>(emb, bufA, bufB, bufC,
                                                     user, pos, neg, out);
}